// round 12
// baseline (speedup 1.0000x reference)
#include <cuda_runtime.h>
#include <cuda_fp16.h>
#include <cstdint>
#include <math.h>

#define NN 50000
#define NE 800000
#define IND 256
#define FDIM 256       // 2 heads * 128
#define SCAN_BLKS 49   // ceil(NN / 1024)
#define GEMM_BX 391    // ceil(NN / 128)

// ---------------- scratch (static __device__, no allocation) ----------------
__device__ __align__(16) __half g_Whh[NN * FDIM];   // 25.6 MB fp16 Wh
__device__ float g_s[NN * 2];
__device__ float g_t[NN * 2];
__device__ __align__(16) int g_deg[NN];
__device__ __align__(16) int g_off[NN + 4];
__device__ __align__(16) int g_cur[NN];
__device__ int g_dst[NE];
__device__ int g_bsum[64];
__device__ int g_bpre[64];

// ---------------- CSR build ----------------
__global__ void k_zero() {
    int i = blockIdx.x * blockDim.x + threadIdx.x;
    if (i < NN) g_deg[i] = 0;
}

__global__ void k_count(const int* __restrict__ ei) {
    int e = blockIdx.x * blockDim.x + threadIdx.x;
    if (e < NE) {
        unsigned s = (unsigned)ei[e];
        if (s < NN) atomicAdd(&g_deg[s], 1);
    }
}

__global__ __launch_bounds__(256) void k_scan1() {
    int b = blockIdx.x, t = threadIdx.x;
    int lane = t & 31, wid = t >> 5;
    int base = b * 1024 + t * 4;

    int v0 = 0, v1 = 0, v2 = 0, v3 = 0;
    if (base + 3 < NN) {
        int4 q = *(const int4*)&g_deg[base];
        v0 = q.x; v1 = q.y; v2 = q.z; v3 = q.w;
    }
    int s = v0 + v1 + v2 + v3;

    int inc = s;
#pragma unroll
    for (int o = 1; o < 32; o <<= 1) {
        int u = __shfl_up_sync(0xffffffffu, inc, o);
        if (lane >= o) inc += u;
    }
    __shared__ int ws[8];
    if (lane == 31) ws[wid] = inc;
    __syncthreads();
    int wpre = 0;
#pragma unroll
    for (int w = 0; w < 8; w++) wpre += (w < wid) ? ws[w] : 0;

    int ex = wpre + inc - s;
    if (base + 3 < NN) {
        int4 o;
        o.x = ex;
        o.y = ex + v0;
        o.z = ex + v0 + v1;
        o.w = ex + v0 + v1 + v2;
        *(int4*)&g_off[base] = o;
    }
    if (t == 255) g_bsum[b] = ex + s;
}

__global__ void k_scan2() {
    int t = threadIdx.x;
    int lane = t & 31, wid = t >> 5;
    int v = (t < SCAN_BLKS) ? g_bsum[t] : 0;
    int inc = v;
#pragma unroll
    for (int o = 1; o < 32; o <<= 1) {
        int u = __shfl_up_sync(0xffffffffu, inc, o);
        if (lane >= o) inc += u;
    }
    __shared__ int w0tot;
    if (wid == 0 && lane == 31) w0tot = inc;
    __syncthreads();
    int ex = inc - v + (wid ? w0tot : 0);
    if (t < SCAN_BLKS) g_bpre[t] = ex;
    if (t == SCAN_BLKS - 1) g_off[NN] = ex + v;
}

__global__ __launch_bounds__(256) void k_scan3() {
    int b = blockIdx.x, t = threadIdx.x;
    int base = b * 1024 + t * 4;
    int p = g_bpre[b];
    if (base + 3 < NN) {
        int4 o = *(const int4*)&g_off[base];
        o.x += p; o.y += p; o.z += p; o.w += p;
        *(int4*)&g_off[base] = o;
        *(int4*)&g_cur[base] = o;
    }
}

__global__ void k_scatter(const int* __restrict__ ei) {
    int e = blockIdx.x * blockDim.x + threadIdx.x;
    if (e < NE) {
        unsigned s = (unsigned)ei[e];
        unsigned d = (unsigned)ei[NE + e];
        if (s < NN && d < NN) {
            int p = atomicAdd(&g_cur[s], 1);
            if (p >= 0 && p < NE) g_dst[p] = (int)d;
        }
    }
}

// ---------------- GEMM v2: BM=128 x BN=128, 8x8 micro-tiles, f32x2 ---------
// Thread (ty,tx): rows {ty*4..+3, 64+ty*4..+3}, cols {tx*4..+3, 64+tx*4..+3}.
__global__ __launch_bounds__(256, 2) void k_gemm(const float* __restrict__ x,
                                                 const float* __restrict__ W,
                                                 const float* __restrict__ b,
                                                 const float* __restrict__ a) {
    __shared__ float xs[32][128];   // [k][row]
    __shared__ float ws[32][128];   // [k][n]
    __shared__ float cb[128], cas[128], cat[128];

    int tid = threadIdx.x;
    int tx = tid & 15, ty = tid >> 4;
    int h = blockIdx.y;
    int row0 = blockIdx.x * 128;

    if (tid < 128) {
        cb[tid]  = b[h * 128 + tid];
        cas[tid] = a[tid];
        cat[tid] = a[128 + tid];
    }

    unsigned long long acc2[8][4];
    unsigned long long zz;
    asm("mov.b64 %0, {%1, %1};" : "=l"(zz) : "r"(0u));
#pragma unroll
    for (int i = 0; i < 8; i++)
#pragma unroll
        for (int j = 0; j < 4; j++) acc2[i][j] = zz;

    int xr = tid & 127;              // row this thread stages
    int xkq = (tid >> 7) * 16;       // k-offset 0 or 16
    int wkr = tid >> 5;              // 0..7
    int wnq = (tid & 31) * 4;        // 0..124

    for (int k0 = 0; k0 < IND; k0 += 32) {
        // ---- x tile: 128 rows x 32 k, transposed ----
        {
            int grow = row0 + xr;
#pragma unroll
            for (int p = 0; p < 4; p++) {
                float4 v = make_float4(0.f, 0.f, 0.f, 0.f);
                if (grow < NN) v = *(const float4*)&x[grow * IND + k0 + xkq + p * 4];
                xs[xkq + p * 4 + 0][xr] = v.x;
                xs[xkq + p * 4 + 1][xr] = v.y;
                xs[xkq + p * 4 + 2][xr] = v.z;
                xs[xkq + p * 4 + 3][xr] = v.w;
            }
        }
        // ---- W tile: 32 k x 128 n ----
        {
#pragma unroll
            for (int p = 0; p < 4; p++) {
                int k = wkr + p * 8;
                *(float4*)&ws[k][wnq] = *(const float4*)&W[(k0 + k) * FDIM + h * 128 + wnq];
            }
        }
        __syncthreads();

#pragma unroll
        for (int kk = 0; kk < 32; kk++) {
            float4 a0v = *(const float4*)&xs[kk][ty * 4];
            float4 a1v = *(const float4*)&xs[kk][64 + ty * 4];
            ulonglong2 b0 = *(const ulonglong2*)&ws[kk][tx * 4];
            ulonglong2 b1 = *(const ulonglong2*)&ws[kk][64 + tx * 4];
            unsigned long long bs[4] = { b0.x, b0.y, b1.x, b1.y };
            float ar[8] = { a0v.x, a0v.y, a0v.z, a0v.w, a1v.x, a1v.y, a1v.z, a1v.w };
#pragma unroll
            for (int i = 0; i < 8; i++) {
                unsigned long long am;
                asm("mov.b64 %0, {%1, %1};" : "=l"(am) : "r"(__float_as_uint(ar[i])));
#pragma unroll
                for (int j = 0; j < 4; j++) {
                    asm("fma.rn.f32x2 %0, %1, %2, %3;"
                        : "=l"(acc2[i][j]) : "l"(am), "l"(bs[j]), "l"(acc2[i][j]));
                }
            }
        }
        __syncthreads();
    }

    // ---- epilogue: bias + fp16 store + s/t dots (width-16 shfl reduce) ----
#pragma unroll
    for (int i = 0; i < 8; i++) {
        int grow = row0 + ((i < 4) ? (ty * 4 + i) : (64 + ty * 4 + (i - 4)));
        float f[8];
#pragma unroll
        for (int j = 0; j < 4; j++) {
            unsigned int lo, hi;
            asm("mov.b64 {%0, %1}, %2;" : "=r"(lo), "=r"(hi) : "l"(acc2[i][j]));
            f[j * 2 + 0] = __uint_as_float(lo);
            f[j * 2 + 1] = __uint_as_float(hi);
        }
        float ps = 0.f, pt = 0.f;
#pragma unroll
        for (int e = 0; e < 8; e++) {
            int c = (e < 4) ? (tx * 4 + e) : (64 + tx * 4 + (e - 4));
            f[e] += cb[c];
            ps += f[e] * cas[c];
            pt += f[e] * cat[c];
        }
#pragma unroll
        for (int off = 8; off > 0; off >>= 1) {
            ps += __shfl_down_sync(0xffffffffu, ps, off, 16);
            pt += __shfl_down_sync(0xffffffffu, pt, off, 16);
        }
        if (grow < NN) {
            __half2 h01 = __floats2half2_rn(f[0], f[1]);
            __half2 h23 = __floats2half2_rn(f[2], f[3]);
            __half2 h45 = __floats2half2_rn(f[4], f[5]);
            __half2 h67 = __floats2half2_rn(f[6], f[7]);
            uint2 u0, u1;
            u0.x = *(unsigned int*)&h01;  u0.y = *(unsigned int*)&h23;
            u1.x = *(unsigned int*)&h45;  u1.y = *(unsigned int*)&h67;
            *(uint2*)&g_Whh[grow * FDIM + h * 128 + tx * 4]      = u0;
            *(uint2*)&g_Whh[grow * FDIM + h * 128 + 64 + tx * 4] = u1;
            if (tx == 0) {
                g_s[grow * 2 + h] = ps;
                g_t[grow * 2 + h] = pt;
            }
        }
    }
}

// ---------------- per-node online softmax + aggregation --------------------
// 1 warp/node; lane owns 8 contiguous halfs (16B) -> 1 LDG.128 per edge/lane.
__global__ __launch_bounds__(512) void k_agg(float* __restrict__ out) {
    int gwarp = (blockIdx.x * blockDim.x + threadIdx.x) >> 5;
    int lane  = threadIdx.x & 31;
    if (gwarp >= NN) return;
    int n = gwarp;
    int start = g_off[n];
    int end   = g_off[n + 1];
    int h     = lane >> 4;
    int col   = lane * 8;

    const uint4* __restrict__ whh = (const uint4*)g_Whh;   // row = 32 uint4

    if (end == start) {  // deg == 0 -> h' = Wh (fp16 source)
        uint4 v = whh[n * 32 + lane];
        const __half2* hp = (const __half2*)&v;
        float2 f0 = __half22float2(hp[0]);
        float2 f1 = __half22float2(hp[1]);
        float2 f2 = __half22float2(hp[2]);
        float2 f3 = __half22float2(hp[3]);
        float4* dst = (float4*)&out[n * FDIM + col];
        dst[0] = make_float4(f0.x, f0.y, f1.x, f1.y);
        dst[1] = make_float4(f2.x, f2.y, f3.x, f3.y);
        return;
    }

    float ss = g_s[n * 2 + h];
    float m = -INFINITY, d = 0.f;
    float f[8];
#pragma unroll
    for (int k = 0; k < 8; k++) f[k] = 0.f;

    int i = start;
    for (; i + 3 < end; i += 4) {
        int d0i = g_dst[i],     d1i = g_dst[i + 1];
        int d2i = g_dst[i + 2], d3i = g_dst[i + 3];
        uint4 v0 = whh[d0i * 32 + lane];
        uint4 v1 = whh[d1i * 32 + lane];
        uint4 v2 = whh[d2i * 32 + lane];
        uint4 v3 = whh[d3i * 32 + lane];
        float t0 = g_t[d0i * 2 + h], t1 = g_t[d1i * 2 + h];
        float t2 = g_t[d2i * 2 + h], t3 = g_t[d3i * 2 + h];

        float e0 = ss + t0; e0 = (e0 > 0.f) ? e0 : 0.2f * e0;
        float e1 = ss + t1; e1 = (e1 > 0.f) ? e1 : 0.2f * e1;
        float e2 = ss + t2; e2 = (e2 > 0.f) ? e2 : 0.2f * e2;
        float e3 = ss + t3; e3 = (e3 > 0.f) ? e3 : 0.2f * e3;

        float nm = fmaxf(fmaxf(m, fmaxf(e0, e1)), fmaxf(e2, e3));
        float c  = __expf(m - nm);
        float w0 = __expf(e0 - nm), w1 = __expf(e1 - nm);
        float w2 = __expf(e2 - nm), w3 = __expf(e3 - nm);
        d = d * c + w0 + w1 + w2 + w3;
        m = nm;

        const uint32_t* p0 = &v0.x;
        const uint32_t* p1 = &v1.x;
        const uint32_t* p2 = &v2.x;
        const uint32_t* p3 = &v3.x;
#pragma unroll
        for (int q = 0; q < 4; q++) {
            float2 a0 = __half22float2(*(const __half2*)&p0[q]);
            float2 a1 = __half22float2(*(const __half2*)&p1[q]);
            float2 a2 = __half22float2(*(const __half2*)&p2[q]);
            float2 a3 = __half22float2(*(const __half2*)&p3[q]);
            f[q * 2 + 0] = f[q * 2 + 0] * c + w0 * a0.x + w1 * a1.x + w2 * a2.x + w3 * a3.x;
            f[q * 2 + 1] = f[q * 2 + 1] * c + w0 * a0.y + w1 * a1.y + w2 * a2.y + w3 * a3.y;
        }
    }
    for (; i < end; i++) {
        int dd = g_dst[i];
        uint4 v = whh[dd * 32 + lane];
        float tt = g_t[dd * 2 + h];
        float e = ss + tt; e = (e > 0.f) ? e : 0.2f * e;
        float nm = fmaxf(m, e);
        float c  = __expf(m - nm);
        float w  = __expf(e - nm);
        d = d * c + w;
        m = nm;
        const uint32_t* p = &v.x;
#pragma unroll
        for (int q = 0; q < 4; q++) {
            float2 av = __half22float2(*(const __half2*)&p[q]);
            f[q * 2 + 0] = f[q * 2 + 0] * c + w * av.x;
            f[q * 2 + 1] = f[q * 2 + 1] * c + w * av.y;
        }
    }

    float inv = 1.f / d;
    float4 o0 = make_float4(f[0] * inv, f[1] * inv, f[2] * inv, f[3] * inv);
    float4 o1 = make_float4(f[4] * inv, f[5] * inv, f[6] * inv, f[7] * inv);
    float4* dst = (float4*)&out[n * FDIM + col];
    dst[0] = o0;
    dst[1] = o1;
}

// ---------------- launch (fork-join: CSR build overlaps GEMM) --------------
static cudaStream_t g_s1 = 0;
static cudaEvent_t  g_evFork = 0, g_evJoin = 0;

extern "C" void kernel_launch(void* const* d_in, const int* in_sizes, int n_in,
                              void* d_out, int out_size) {
    const float* x  = (const float*)d_in[0];
    const int*   ei = (const int*)d_in[1];     // int32: JAX x64-disabled
    const float* W  = (const float*)d_in[2];
    const float* b  = (const float*)d_in[3];
    const float* a  = (const float*)d_in[4];
    float*       out = (float*)d_out;

    if (g_s1 == 0) {   // one-time resource setup (first call is eager, pre-capture)
        cudaStreamCreateWithFlags(&g_s1, cudaStreamNonBlocking);
        cudaEventCreateWithFlags(&g_evFork, cudaEventDisableTiming);
        cudaEventCreateWithFlags(&g_evJoin, cudaEventDisableTiming);
    }

    // fork: CSR chain on s1, independent of GEMM
    cudaEventRecord(g_evFork, 0);
    cudaStreamWaitEvent(g_s1, g_evFork, 0);

    k_zero<<<(NN + 255) / 256, 256, 0, g_s1>>>();
    k_count<<<(NE + 255) / 256, 256, 0, g_s1>>>(ei);
    k_scan1<<<SCAN_BLKS, 256, 0, g_s1>>>();
    k_scan2<<<1, 64, 0, g_s1>>>();
    k_scan3<<<SCAN_BLKS, 256, 0, g_s1>>>();
    k_scatter<<<(NE + 255) / 256, 256, 0, g_s1>>>(ei);
    cudaEventRecord(g_evJoin, g_s1);

    // GEMM on the main stream, concurrent with the CSR chain
    dim3 gg(GEMM_BX, 2);
    k_gemm<<<gg, 256>>>(x, W, b, a);

    // join, then aggregate
    cudaStreamWaitEvent(0, g_evJoin, 0);
    k_agg<<<(NN * 32 + 511) / 512, 512>>>(out);
}

// round 13
// speedup vs baseline: 1.0322x; 1.0322x over previous
#include <cuda_runtime.h>
#include <cuda_fp16.h>
#include <cstdint>
#include <math.h>

#define NN 50000
#define NE 800000
#define IND 256
#define FDIM 256       // 2 heads * 128
#define SCAN_BLKS 49   // ceil(NN / 1024)

// ---------------- scratch (static __device__, no allocation) ----------------
__device__ __align__(16) __half g_Whh[NN * FDIM];   // 25.6 MB fp16 Wh
__device__ float g_s[NN * 2];
__device__ float g_t[NN * 2];
__device__ __align__(16) int g_deg[NN];
__device__ __align__(16) int g_off[NN + 4];
__device__ __align__(16) int g_cur[NN];
__device__ int g_dst[NE];
__device__ int g_bsum[64];
__device__ int g_bpre[64];

// ---------------- CSR build ----------------
__global__ void k_zero() {
    int i = blockIdx.x * blockDim.x + threadIdx.x;
    if (i < NN) g_deg[i] = 0;
}

__global__ void k_count(const int* __restrict__ ei) {
    int e = blockIdx.x * blockDim.x + threadIdx.x;
    if (e < NE) {
        unsigned s = (unsigned)ei[e];
        if (s < NN) atomicAdd(&g_deg[s], 1);
    }
}

__global__ __launch_bounds__(256) void k_scan1() {
    int b = blockIdx.x, t = threadIdx.x;
    int lane = t & 31, wid = t >> 5;
    int base = b * 1024 + t * 4;

    int v0 = 0, v1 = 0, v2 = 0, v3 = 0;
    if (base + 3 < NN) {
        int4 q = *(const int4*)&g_deg[base];
        v0 = q.x; v1 = q.y; v2 = q.z; v3 = q.w;
    }
    int s = v0 + v1 + v2 + v3;

    int inc = s;
#pragma unroll
    for (int o = 1; o < 32; o <<= 1) {
        int u = __shfl_up_sync(0xffffffffu, inc, o);
        if (lane >= o) inc += u;
    }
    __shared__ int ws[8];
    if (lane == 31) ws[wid] = inc;
    __syncthreads();
    int wpre = 0;
#pragma unroll
    for (int w = 0; w < 8; w++) wpre += (w < wid) ? ws[w] : 0;

    int ex = wpre + inc - s;
    if (base + 3 < NN) {
        int4 o;
        o.x = ex;
        o.y = ex + v0;
        o.z = ex + v0 + v1;
        o.w = ex + v0 + v1 + v2;
        *(int4*)&g_off[base] = o;
    }
    if (t == 255) g_bsum[b] = ex + s;
}

__global__ void k_scan2() {
    int t = threadIdx.x;
    int lane = t & 31, wid = t >> 5;
    int v = (t < SCAN_BLKS) ? g_bsum[t] : 0;
    int inc = v;
#pragma unroll
    for (int o = 1; o < 32; o <<= 1) {
        int u = __shfl_up_sync(0xffffffffu, inc, o);
        if (lane >= o) inc += u;
    }
    __shared__ int w0tot;
    if (wid == 0 && lane == 31) w0tot = inc;
    __syncthreads();
    int ex = inc - v + (wid ? w0tot : 0);
    if (t < SCAN_BLKS) g_bpre[t] = ex;
    if (t == SCAN_BLKS - 1) g_off[NN] = ex + v;
}

__global__ __launch_bounds__(256) void k_scan3() {
    int b = blockIdx.x, t = threadIdx.x;
    int base = b * 1024 + t * 4;
    int p = g_bpre[b];
    if (base + 3 < NN) {
        int4 o = *(const int4*)&g_off[base];
        o.x += p; o.y += p; o.z += p; o.w += p;
        *(int4*)&g_off[base] = o;
        *(int4*)&g_cur[base] = o;
    }
}

__global__ void k_scatter(const int* __restrict__ ei) {
    int e = blockIdx.x * blockDim.x + threadIdx.x;
    if (e < NE) {
        unsigned s = (unsigned)ei[e];
        unsigned d = (unsigned)ei[NE + e];
        if (s < NN && d < NN) {
            int p = atomicAdd(&g_cur[s], 1);
            if (p >= 0 && p < NE) g_dst[p] = (int)d;
        }
    }
}

// ---------------- GEMM v3: BM=64 x BN=128, row-paired f32x2 ----------------
// acc[i][j] = {row 2i, row 2i+1} x col j. A pairs load directly as LDS.128
// (rows contiguous in xs[k][row]); only B needs 4 dup-movs per k-step.
// Inner loop: 3 LDS.128 + 4 MOV + 16 FFMA2 = 23 slots vs 32 FMA cycles.
__global__ __launch_bounds__(256) void k_gemm(const float* __restrict__ x,
                                              const float* __restrict__ W,
                                              const float* __restrict__ b,
                                              const float* __restrict__ a) {
    __shared__ float xs[32][68];   // xs[k][row]; 68*4=272B stride, 16B aligned
    __shared__ float ws[32][128];  // ws[k][n]

    int tid  = threadIdx.x;
    int h    = blockIdx.y;                 // head / 128-col tile
    int row0 = blockIdx.x * 64;
    int tr   = tid >> 5;                   // warp id: rows tr*8 .. tr*8+7
    int tc   = tid & 31;                   // cols tc*4 .. tc*4+3 (within head)

    unsigned long long acc2[4][4];         // [row pair][col]
    unsigned long long zz;
    asm("mov.b64 %0, {%1, %1};" : "=l"(zz) : "r"(0u));
#pragma unroll
    for (int i = 0; i < 4; i++)
#pragma unroll
        for (int j = 0; j < 4; j++) acc2[i][j] = zz;

    for (int k0 = 0; k0 < IND; k0 += 32) {
        // load x tile (64 rows x 32 k), transposed into xs[k][row]
#pragma unroll
        for (int q = 0; q < 2; q++) {
            int idx  = tid * 2 + q;
            int r    = idx >> 3;
            int kq   = (idx & 7) << 2;
            int grow = row0 + r;
            float4 xv = make_float4(0.f, 0.f, 0.f, 0.f);
            if (grow < NN) xv = *(const float4*)&x[grow * IND + k0 + kq];
            xs[kq + 0][r] = xv.x;
            xs[kq + 1][r] = xv.y;
            xs[kq + 2][r] = xv.z;
            xs[kq + 3][r] = xv.w;
        }
        // load W tile (32 k x 128 n)
        {
            int kr = tid >> 5;
            int nq = (tid & 31) << 2;
#pragma unroll
            for (int p = 0; p < 4; p++) {
                int k = kr + p * 8;
                *(float4*)&ws[k][nq] = *(const float4*)&W[(k0 + k) * FDIM + h * 128 + nq];
            }
        }
        __syncthreads();
#pragma unroll
        for (int kk = 0; kk < 32; kk++) {
            // A: 8 contiguous rows as 4 f32x2 pairs (broadcast within warp)
            ulonglong2 a01 = *(const ulonglong2*)&xs[kk][tr * 8];
            ulonglong2 a23 = *(const ulonglong2*)&xs[kk][tr * 8 + 4];
            unsigned long long as_[4] = { a01.x, a01.y, a23.x, a23.y };
            // B: 4 cols, duplicated into both lanes of f32x2
            float4 bv = *(const float4*)&ws[kk][tc * 4];
            unsigned long long bd[4];
            asm("mov.b64 %0, {%1, %1};" : "=l"(bd[0]) : "r"(__float_as_uint(bv.x)));
            asm("mov.b64 %0, {%1, %1};" : "=l"(bd[1]) : "r"(__float_as_uint(bv.y)));
            asm("mov.b64 %0, {%1, %1};" : "=l"(bd[2]) : "r"(__float_as_uint(bv.z)));
            asm("mov.b64 %0, {%1, %1};" : "=l"(bd[3]) : "r"(__float_as_uint(bv.w)));
#pragma unroll
            for (int i = 0; i < 4; i++) {
#pragma unroll
                for (int j = 0; j < 4; j++) {
                    asm("fma.rn.f32x2 %0, %1, %2, %3;"
                        : "=l"(acc2[i][j]) : "l"(as_[i]), "l"(bd[j]), "l"(acc2[i][j]));
                }
            }
        }
        __syncthreads();
    }

    // epilogue: bias, fp16 store, fused s/t dot + warp reduce
    float4 bb = *(const float4*)&b[h * 128 + tc * 4];
    float as0 = a[tc * 4 + 0], as1 = a[tc * 4 + 1], as2 = a[tc * 4 + 2], as3 = a[tc * 4 + 3];
    float at0 = a[128 + tc * 4 + 0], at1 = a[128 + tc * 4 + 1];
    float at2 = a[128 + tc * 4 + 2], at3 = a[128 + tc * 4 + 3];

#pragma unroll
    for (int i = 0; i < 4; i++) {
        unsigned int lo[4], hi[4];
#pragma unroll
        for (int j = 0; j < 4; j++) {
            asm("mov.b64 {%0, %1}, %2;" : "=r"(lo[j]), "=r"(hi[j]) : "l"(acc2[i][j]));
        }
#pragma unroll
        for (int half = 0; half < 2; half++) {
            int grow = row0 + tr * 8 + 2 * i + half;
            const unsigned int* src = half ? hi : lo;
            float f0 = __uint_as_float(src[0]) + bb.x;
            float f1 = __uint_as_float(src[1]) + bb.y;
            float f2 = __uint_as_float(src[2]) + bb.z;
            float f3 = __uint_as_float(src[3]) + bb.w;
            float ps = f0 * as0 + f1 * as1 + f2 * as2 + f3 * as3;
            float pt = f0 * at0 + f1 * at1 + f2 * at2 + f3 * at3;
#pragma unroll
            for (int off = 16; off > 0; off >>= 1) {
                ps += __shfl_down_sync(0xffffffffu, ps, off);
                pt += __shfl_down_sync(0xffffffffu, pt, off);
            }
            if (grow < NN) {
                __half2 h01 = __floats2half2_rn(f0, f1);
                __half2 h23 = __floats2half2_rn(f2, f3);
                uint2 u;
                u.x = *(unsigned int*)&h01;
                u.y = *(unsigned int*)&h23;
                *(uint2*)&g_Whh[grow * FDIM + h * 128 + tc * 4] = u;
                if (tc == 0) {
                    g_s[grow * 2 + h] = ps;
                    g_t[grow * 2 + h] = pt;
                }
            }
        }
    }
}

// ---------------- per-node online softmax + aggregation --------------------
// 1 warp/node; lane owns 8 contiguous halfs (16B) -> 1 LDG.128 per edge/lane.
__global__ __launch_bounds__(512) void k_agg(float* __restrict__ out) {
    int gwarp = (blockIdx.x * blockDim.x + threadIdx.x) >> 5;
    int lane  = threadIdx.x & 31;
    if (gwarp >= NN) return;
    int n = gwarp;
    int start = g_off[n];
    int end   = g_off[n + 1];
    int h     = lane >> 4;
    int col   = lane * 8;

    const uint4* __restrict__ whh = (const uint4*)g_Whh;   // row = 32 uint4

    if (end == start) {  // deg == 0 -> h' = Wh (fp16 source)
        uint4 v = whh[n * 32 + lane];
        const __half2* hp = (const __half2*)&v;
        float2 f0 = __half22float2(hp[0]);
        float2 f1 = __half22float2(hp[1]);
        float2 f2 = __half22float2(hp[2]);
        float2 f3 = __half22float2(hp[3]);
        float4* dst = (float4*)&out[n * FDIM + col];
        dst[0] = make_float4(f0.x, f0.y, f1.x, f1.y);
        dst[1] = make_float4(f2.x, f2.y, f3.x, f3.y);
        return;
    }

    float ss = g_s[n * 2 + h];
    float m = -INFINITY, d = 0.f;
    float f[8];
#pragma unroll
    for (int k = 0; k < 8; k++) f[k] = 0.f;

    int i = start;
    for (; i + 3 < end; i += 4) {
        int d0i = g_dst[i],     d1i = g_dst[i + 1];
        int d2i = g_dst[i + 2], d3i = g_dst[i + 3];
        uint4 v0 = whh[d0i * 32 + lane];
        uint4 v1 = whh[d1i * 32 + lane];
        uint4 v2 = whh[d2i * 32 + lane];
        uint4 v3 = whh[d3i * 32 + lane];
        float t0 = g_t[d0i * 2 + h], t1 = g_t[d1i * 2 + h];
        float t2 = g_t[d2i * 2 + h], t3 = g_t[d3i * 2 + h];

        float e0 = ss + t0; e0 = (e0 > 0.f) ? e0 : 0.2f * e0;
        float e1 = ss + t1; e1 = (e1 > 0.f) ? e1 : 0.2f * e1;
        float e2 = ss + t2; e2 = (e2 > 0.f) ? e2 : 0.2f * e2;
        float e3 = ss + t3; e3 = (e3 > 0.f) ? e3 : 0.2f * e3;

        float nm = fmaxf(fmaxf(m, fmaxf(e0, e1)), fmaxf(e2, e3));
        float c  = __expf(m - nm);
        float w0 = __expf(e0 - nm), w1 = __expf(e1 - nm);
        float w2 = __expf(e2 - nm), w3 = __expf(e3 - nm);
        d = d * c + w0 + w1 + w2 + w3;
        m = nm;

        const uint32_t* p0 = &v0.x;
        const uint32_t* p1 = &v1.x;
        const uint32_t* p2 = &v2.x;
        const uint32_t* p3 = &v3.x;
#pragma unroll
        for (int q = 0; q < 4; q++) {
            float2 a0 = __half22float2(*(const __half2*)&p0[q]);
            float2 a1 = __half22float2(*(const __half2*)&p1[q]);
            float2 a2 = __half22float2(*(const __half2*)&p2[q]);
            float2 a3 = __half22float2(*(const __half2*)&p3[q]);
            f[q * 2 + 0] = f[q * 2 + 0] * c + w0 * a0.x + w1 * a1.x + w2 * a2.x + w3 * a3.x;
            f[q * 2 + 1] = f[q * 2 + 1] * c + w0 * a0.y + w1 * a1.y + w2 * a2.y + w3 * a3.y;
        }
    }
    for (; i < end; i++) {
        int dd = g_dst[i];
        uint4 v = whh[dd * 32 + lane];
        float tt = g_t[dd * 2 + h];
        float e = ss + tt; e = (e > 0.f) ? e : 0.2f * e;
        float nm = fmaxf(m, e);
        float c  = __expf(m - nm);
        float w  = __expf(e - nm);
        d = d * c + w;
        m = nm;
        const uint32_t* p = &v.x;
#pragma unroll
        for (int q = 0; q < 4; q++) {
            float2 av = __half22float2(*(const __half2*)&p[q]);
            f[q * 2 + 0] = f[q * 2 + 0] * c + w * av.x;
            f[q * 2 + 1] = f[q * 2 + 1] * c + w * av.y;
        }
    }

    float inv = 1.f / d;
    float4 o0 = make_float4(f[0] * inv, f[1] * inv, f[2] * inv, f[3] * inv);
    float4 o1 = make_float4(f[4] * inv, f[5] * inv, f[6] * inv, f[7] * inv);
    float4* dst = (float4*)&out[n * FDIM + col];
    dst[0] = o0;
    dst[1] = o1;
}

// ---------------- launch (fork-join: CSR build overlaps GEMM) --------------
static cudaStream_t g_s1 = 0;
static cudaEvent_t  g_evFork = 0, g_evJoin = 0;

extern "C" void kernel_launch(void* const* d_in, const int* in_sizes, int n_in,
                              void* d_out, int out_size) {
    const float* x  = (const float*)d_in[0];
    const int*   ei = (const int*)d_in[1];     // int32: JAX x64-disabled
    const float* W  = (const float*)d_in[2];
    const float* b  = (const float*)d_in[3];
    const float* a  = (const float*)d_in[4];
    float*       out = (float*)d_out;

    if (g_s1 == 0) {   // one-time resource setup (first call is eager, pre-capture)
        cudaStreamCreateWithFlags(&g_s1, cudaStreamNonBlocking);
        cudaEventCreateWithFlags(&g_evFork, cudaEventDisableTiming);
        cudaEventCreateWithFlags(&g_evJoin, cudaEventDisableTiming);
    }

    // fork: CSR chain on s1, independent of GEMM
    cudaEventRecord(g_evFork, 0);
    cudaStreamWaitEvent(g_s1, g_evFork, 0);

    k_zero<<<(NN + 255) / 256, 256, 0, g_s1>>>();
    k_count<<<(NE + 255) / 256, 256, 0, g_s1>>>(ei);
    k_scan1<<<SCAN_BLKS, 256, 0, g_s1>>>();
    k_scan2<<<1, 64, 0, g_s1>>>();
    k_scan3<<<SCAN_BLKS, 256, 0, g_s1>>>();
    k_scatter<<<(NE + 255) / 256, 256, 0, g_s1>>>(ei);
    cudaEventRecord(g_evJoin, g_s1);

    // GEMM on the main stream, concurrent with the CSR chain
    dim3 gg((NN + 63) / 64, 2);
    k_gemm<<<gg, 256>>>(x, W, b, a);

    // join, then aggregate
    cudaStreamWaitEvent(0, g_evJoin, 0);
    k_agg<<<(NN * 32 + 511) / 512, 512>>>(out);
}